// round 4
// baseline (speedup 1.0000x reference)
#include <cuda_runtime.h>
#include <math.h>

// ---------------------------------------------------------------------------
// Problem constants
//   B=8, N=2048, DA=768, DB=1024
// ---------------------------------------------------------------------------
#define BATCH 8
#define SEQ   2048
#define DA    768
#define DB    1024

// Scratch (device globals — module-load allocation, allowed by the harness).
// g_q is reused for the attention output (q is dead once scores exist).
__device__ float g_q   [BATCH * SEQ * DB];   // 64 MB (q, later attn)
__device__ float g_k   [BATCH * SEQ * DB];   // 64 MB
__device__ float g_v   [BATCH * SEQ * DB];   // 64 MB
__device__ float g_s   [BATCH * SEQ * SEQ];  // 128 MB
__device__ float g_xb2 [BATCH * SEQ * DB];   // 64 MB

// ---------------------------------------------------------------------------
// Tiled SGEMM: C = alpha * A @ op(B) [+ bias] [+ res]
//   A: [M,K] row-major
//   B: TRANSB ? [N,K] row-major (C=A*B^T) : [K,N] row-major
//   bias: [N] per-output-column, res: same shape/stride as C
//   batched over blockIdx.z with element strides sA,sB,sC (res uses sC).
// Tile 128x128x16, 256 threads, 8x8 per-thread (as 2x2 quadrants of 4x4).
// Requires: M%128==0, N%128==0, K%16==0  (true for all our shapes).
// ---------------------------------------------------------------------------
#define BM 128
#define BN 128
#define BKK 16

template<bool TRANSB, bool HAS_BIAS, bool HAS_RES>
__global__ __launch_bounds__(256)
void gemm_kernel(const float* __restrict__ A,
                 const float* __restrict__ Bm,
                 const float* __restrict__ bias,
                 const float* __restrict__ res,
                 float* __restrict__ C,
                 int M, int N, int K, float alpha,
                 size_t sA, size_t sB, size_t sC)
{
    const int bz = blockIdx.z;
    A  += (size_t)bz * sA;
    Bm += (size_t)bz * sB;
    C  += (size_t)bz * sC;
    const float* __restrict__ R = HAS_RES ? (res + (size_t)bz * sC) : nullptr;

    __shared__ float As[BKK][BM];
    __shared__ float Bs[BKK][BN];

    const int row0 = blockIdx.y * BM;
    const int col0 = blockIdx.x * BN;
    const int tid  = threadIdx.x;
    const int lane = tid & 31;
    const int warp = tid >> 5;
    // Warp arranged as 4 (rows) x 8 (cols) threads; 8 warps as 4x2.
    // => within a warp, regB spans 8 distinct float4s (32 banks, no conflict),
    //    regA spans 4 distinct float4s (broadcast), no conflicts.
    const int tn = ((warp & 1) << 3) + (lane & 7);   // 0..15
    const int tm = ((warp >> 1) << 2) + (lane >> 3); // 0..15

    float acc[2][2][4][4];
    #pragma unroll
    for (int a = 0; a < 2; a++)
        #pragma unroll
        for (int b = 0; b < 4; b++)
            #pragma unroll
            for (int c = 0; c < 2; c++)
                #pragma unroll
                for (int d = 0; d < 4; d++)
                    acc[a][c][b][d] = 0.0f;

    for (int kk = 0; kk < K; kk += BKK) {
        // ---- load A tile (BM x BKK), store transposed to As[k][m] ----
        #pragma unroll
        for (int i = 0; i < 2; i++) {
            int f  = tid + i * 256;        // float4 index, 0..511
            int ar = f >> 2;               // 0..127 (row within tile)
            int ac = (f & 3) << 2;         // 0,4,8,12 (k within tile)
            float4 val = *(const float4*)&A[(size_t)(row0 + ar) * K + kk + ac];
            As[ac + 0][ar] = val.x;
            As[ac + 1][ar] = val.y;
            As[ac + 2][ar] = val.z;
            As[ac + 3][ar] = val.w;
        }
        // ---- load B tile ----
        if (TRANSB) {
            #pragma unroll
            for (int i = 0; i < 2; i++) {
                int f  = tid + i * 256;
                int br = f >> 2;           // 0..127 (n within tile)
                int bc = (f & 3) << 2;     // k within tile
                float4 val = *(const float4*)&Bm[(size_t)(col0 + br) * K + kk + bc];
                Bs[bc + 0][br] = val.x;
                Bs[bc + 1][br] = val.y;
                Bs[bc + 2][br] = val.z;
                Bs[bc + 3][br] = val.w;
            }
        } else {
            #pragma unroll
            for (int i = 0; i < 2; i++) {
                int f  = tid + i * 256;
                int br = f >> 5;           // 0..15 (k within tile)
                int bc = (f & 31) << 2;    // 0..124 (n within tile)
                *(float4*)&Bs[br][bc] =
                    *(const float4*)&Bm[(size_t)(kk + br) * N + col0 + bc];
            }
        }
        __syncthreads();

        // ---- compute ----
        #pragma unroll
        for (int k = 0; k < BKK; k++) {
            float ra[2][4], rb[2][4];
            #pragma unroll
            for (int h = 0; h < 2; h++) {
                *(float4*)ra[h] = *(const float4*)&As[k][h * 64 + tm * 4];
                *(float4*)rb[h] = *(const float4*)&Bs[k][h * 64 + tn * 4];
            }
            #pragma unroll
            for (int im = 0; im < 2; im++)
                #pragma unroll
                for (int in = 0; in < 2; in++)
                    #pragma unroll
                    for (int i = 0; i < 4; i++)
                        #pragma unroll
                        for (int j = 0; j < 4; j++)
                            acc[im][in][i][j] += ra[im][i] * rb[in][j];
        }
        __syncthreads();
    }

    // ---- epilogue ----
    #pragma unroll
    for (int im = 0; im < 2; im++) {
        #pragma unroll
        for (int i = 0; i < 4; i++) {
            int r = row0 + im * 64 + tm * 4 + i;
            #pragma unroll
            for (int in = 0; in < 2; in++) {
                int c = col0 + in * 64 + tn * 4;
                float4 o;
                o.x = acc[im][in][i][0] * alpha;
                o.y = acc[im][in][i][1] * alpha;
                o.z = acc[im][in][i][2] * alpha;
                o.w = acc[im][in][i][3] * alpha;
                if (HAS_BIAS) {
                    o.x += bias[c + 0];
                    o.y += bias[c + 1];
                    o.z += bias[c + 2];
                    o.w += bias[c + 3];
                }
                if (HAS_RES) {
                    float4 rv = *(const float4*)&R[(size_t)r * N + c];
                    o.x += rv.x; o.y += rv.y; o.z += rv.z; o.w += rv.w;
                }
                *(float4*)&C[(size_t)r * N + c] = o;
            }
        }
    }
}

// ---------------------------------------------------------------------------
// Row softmax over 2048 columns. One block (256 threads) per row.
// Single global read + single global write (values kept in registers).
// ---------------------------------------------------------------------------
__global__ __launch_bounds__(256)
void softmax_kernel(float* __restrict__ S)
{
    float4* row = (float4*)(S + (size_t)blockIdx.x * SEQ);
    const int tid = threadIdx.x;
    __shared__ float red[256];

    float4 v0 = row[tid];
    float4 v1 = row[tid + 256];

    float m = fmaxf(fmaxf(fmaxf(v0.x, v0.y), fmaxf(v0.z, v0.w)),
                    fmaxf(fmaxf(v1.x, v1.y), fmaxf(v1.z, v1.w)));
    red[tid] = m;
    __syncthreads();
    #pragma unroll
    for (int s = 128; s > 0; s >>= 1) {
        if (tid < s) red[tid] = fmaxf(red[tid], red[tid + s]);
        __syncthreads();
    }
    m = red[0];
    __syncthreads();

    v0.x = __expf(v0.x - m); v0.y = __expf(v0.y - m);
    v0.z = __expf(v0.z - m); v0.w = __expf(v0.w - m);
    v1.x = __expf(v1.x - m); v1.y = __expf(v1.y - m);
    v1.z = __expf(v1.z - m); v1.w = __expf(v1.w - m);

    float sum = (v0.x + v0.y + v0.z + v0.w) + (v1.x + v1.y + v1.z + v1.w);
    red[tid] = sum;
    __syncthreads();
    #pragma unroll
    for (int s = 128; s > 0; s >>= 1) {
        if (tid < s) red[tid] += red[tid + s];
        __syncthreads();
    }
    float inv = 1.0f / red[0];

    v0.x *= inv; v0.y *= inv; v0.z *= inv; v0.w *= inv;
    v1.x *= inv; v1.y *= inv; v1.z *= inv; v1.w *= inv;
    row[tid]       = v0;
    row[tid + 256] = v1;
}

// ---------------------------------------------------------------------------
// Launch plumbing
// ---------------------------------------------------------------------------
static inline void gemm_proj(const float* A, const float* W, const float* b,
                             float* C, int M, int N, int K)
{
    dim3 grid(N / BN, M / BM, 1);
    gemm_kernel<false, true, false><<<grid, 256>>>(A, W, b, nullptr, C,
                                                   M, N, K, 1.0f, 0, 0, 0);
}

extern "C" void kernel_launch(void* const* d_in, const int* in_sizes, int n_in,
                              void* d_out, int out_size)
{
    const float* x_a   = (const float*)d_in[0];
    const float* x_b   = (const float*)d_in[1];
    const float* sa_wq = (const float*)d_in[2];
    const float* sa_bq = (const float*)d_in[3];
    const float* sa_wk = (const float*)d_in[4];
    const float* sa_bk = (const float*)d_in[5];
    const float* sa_wv = (const float*)d_in[6];
    const float* sa_bv = (const float*)d_in[7];
    const float* sa_wo = (const float*)d_in[8];
    const float* sa_bo = (const float*)d_in[9];
    const float* ca_wq = (const float*)d_in[10];
    const float* ca_bq = (const float*)d_in[11];
    const float* ca_wk = (const float*)d_in[12];
    const float* ca_bk = (const float*)d_in[13];
    const float* ca_wv = (const float*)d_in[14];
    const float* ca_bv = (const float*)d_in[15];
    const float* ca_wo = (const float*)d_in[16];
    const float* ca_bo = (const float*)d_in[17];
    float* out = (float*)d_out;

    float *q, *k, *v, *s, *xb2;
    cudaGetSymbolAddress((void**)&q,    g_q);
    cudaGetSymbolAddress((void**)&k,    g_k);
    cudaGetSymbolAddress((void**)&v,    g_v);
    cudaGetSymbolAddress((void**)&s,    g_s);
    cudaGetSymbolAddress((void**)&xb2,  g_xb2);
    float* attn = q;   // alias: q is dead once scores are computed

    const int M  = BATCH * SEQ;                 // 16384
    const size_t qkvStride = (size_t)SEQ * DB;  // 2048*1024
    const size_t sStride   = (size_t)SEQ * SEQ; // 2048*2048

    // ================= Self-attention on x_b =================
    gemm_proj(x_b, sa_wq, sa_bq, q, M, DB, DB);
    gemm_proj(x_b, sa_wk, sa_bk, k, M, DB, DB);
    gemm_proj(x_b, sa_wv, sa_bv, v, M, DB, DB);

    {   // scores = Q @ K^T / sqrt(DB), batched
        dim3 grid(SEQ / BN, SEQ / BM, BATCH);
        gemm_kernel<true, false, false><<<grid, 256>>>(
            q, k, nullptr, nullptr, s, SEQ, SEQ, DB,
            1.0f / sqrtf((float)DB), qkvStride, qkvStride, sStride);
    }
    softmax_kernel<<<BATCH * SEQ, 256>>>(s);
    {   // attn = P @ V, batched (writes into the dead q buffer)
        dim3 grid(DB / BN, SEQ / BM, BATCH);
        gemm_kernel<false, false, false><<<grid, 256>>>(
            s, v, nullptr, nullptr, attn, SEQ, DB, SEQ,
            1.0f, sStride, qkvStride, qkvStride);
    }
    {   // xb2 = x_b + attn @ Wo + bo
        dim3 grid(DB / BN, M / BM, 1);
        gemm_kernel<false, true, true><<<grid, 256>>>(
            attn, sa_wo, sa_bo, x_b, xb2, M, DB, DB, 1.0f, 0, 0, 0);
    }

    // ================= Cross-attention =================
    gemm_proj(x_a, ca_wq, ca_bq, q, M, DB, DA);   // q from x_a (K = 768)
    gemm_proj(xb2, ca_wk, ca_bk, k, M, DB, DB);
    gemm_proj(xb2, ca_wv, ca_bv, v, M, DB, DB);

    {   // scores = Q @ K^T / sqrt(DA)
        dim3 grid(SEQ / BN, SEQ / BM, BATCH);
        gemm_kernel<true, false, false><<<grid, 256>>>(
            q, k, nullptr, nullptr, s, SEQ, SEQ, DB,
            1.0f / sqrtf((float)DA), qkvStride, qkvStride, sStride);
    }
    softmax_kernel<<<BATCH * SEQ, 256>>>(s);
    {   // attn = P @ V (into dead q buffer)
        dim3 grid(DB / BN, SEQ / BM, BATCH);
        gemm_kernel<false, false, false><<<grid, 256>>>(
            s, v, nullptr, nullptr, attn, SEQ, DB, SEQ,
            1.0f, sStride, qkvStride, qkvStride);
    }
    {   // out = xb2 + attn @ Wo + bo
        dim3 grid(DB / BN, M / BM, 1);
        gemm_kernel<false, true, true><<<grid, 256>>>(
            attn, ca_wo, ca_bo, xb2, out, M, DB, DB, 1.0f, 0, 0, 0);
    }
}

// round 8
// speedup vs baseline: 2.0070x; 2.0070x over previous
#include <cuda_runtime.h>
#include <cuda_bf16.h>
#include <cstdint>
#include <math.h>

#define BATCH 8
#define SEQ   2048
#define DA    768
#define DB    1024

// ---------------- scratch (device globals; module-load allocation) ---------
__device__ float g_q   [BATCH * SEQ * DB];   // q, later attn (aliased)
__device__ float g_k   [BATCH * SEQ * DB];
__device__ float g_v   [BATCH * SEQ * DB];
__device__ float g_vt  [BATCH * SEQ * DB];   // V transposed per batch [DB][SEQ]
__device__ float g_s   [BATCH * SEQ * SEQ];
__device__ float g_xb2 [BATCH * SEQ * DB];
__device__ float g_wt  [8 * DB * DB];        // transposed weights

// ---------------------------------------------------------------------------
// bf16 hi/lo split helpers (Dekker): x ~= hi + lo, error ~2^-17 |x|
// ---------------------------------------------------------------------------
__device__ __forceinline__ void split_bf16(float x, __nv_bfloat16& h, __nv_bfloat16& l) {
    h = __float2bfloat16_rn(x);
    l = __float2bfloat16_rn(x - __bfloat162float(h));
}

// pack two bf16 into b32
__device__ __forceinline__ uint32_t pack2(__nv_bfloat16 a, __nv_bfloat16 b) {
    __nv_bfloat162 t;
    t.x = a; t.y = b;
    return *(uint32_t*)&t;
}

#define MMA_BF16(acc, Af, Bf)                                                  \
    asm volatile(                                                              \
        "mma.sync.aligned.m16n8k16.row.col.f32.bf16.bf16.f32 "                 \
        "{%0,%1,%2,%3},{%4,%5,%6,%7},{%8,%9},{%0,%1,%2,%3};"                   \
        : "+f"((acc)[0]), "+f"((acc)[1]), "+f"((acc)[2]), "+f"((acc)[3])       \
        : "r"((Af)[0]), "r"((Af)[1]), "r"((Af)[2]), "r"((Af)[3]),              \
          "r"((Bf)[0]), "r"((Bf)[1]))

// ---------------------------------------------------------------------------
// Tensor-core GEMM via mma.sync (bf16, 3-pass hi/lo compensation):
//   C = alpha * A @ B^T  [+ bias] [+ res]
//   A: [M,K] row-major fp32, B: [N,K] row-major fp32. Batched over blockIdx.z.
//   CTA tile 128x128, K-chunk 32. 256 threads = 8 warps as 2(M) x 4(N),
//   warp tile 64x32, mma m16n8k16. Requires M%128==0, N%128==0, K%32==0.
// SMEM: 4 arrays (Ah, Al, Bh, Bl), each [128 rows][40 bf16] (32 data + 8 pad).
//   Row stride 40 bf16 = 20 banks -> all fragment loads are conflict-free.
// ---------------------------------------------------------------------------
#define KSTR 20              // row stride in b32 units (40 bf16)
#define ARR_B32 (128 * KSTR) // b32 words per array
#define SMEM_DYN (4 * ARR_B32 * 4)

template<bool HAS_BIAS, bool HAS_RES>
__global__ __launch_bounds__(256)
void mma_gemm(const float* __restrict__ A, const float* __restrict__ Bm,
              const float* __restrict__ bias, const float* __restrict__ res,
              float* __restrict__ C, int M, int N, int K, float alpha,
              size_t sA, size_t sB, size_t sC)
{
    extern __shared__ uint32_t sm[];
    uint32_t* ah32 = sm;
    uint32_t* al32 = sm + ARR_B32;
    uint32_t* bh32 = sm + 2 * ARR_B32;
    uint32_t* bl32 = sm + 3 * ARR_B32;

    const int bz = blockIdx.z;
    A  += (size_t)bz * sA;
    Bm += (size_t)bz * sB;
    C  += (size_t)bz * sC;
    const float* __restrict__ R = HAS_RES ? (res + (size_t)bz * sC) : nullptr;

    const int row0 = blockIdx.y * 128;
    const int col0 = blockIdx.x * 128;
    const int tid  = threadIdx.x;
    const int wid  = tid >> 5;
    const int lane = tid & 31;
    const int wm   = wid >> 2;          // 0..1  (M)
    const int wn   = wid & 3;           // 0..3  (N)
    const int lr   = lane >> 2;         // 0..7
    const int lc   = lane & 3;          // 0..3

    float acc[4][4][4];
    #pragma unroll
    for (int a = 0; a < 4; a++)
        #pragma unroll
        for (int b = 0; b < 4; b++)
            #pragma unroll
            for (int c = 0; c < 4; c++)
                acc[a][b][c] = 0.0f;

    const int nCh = K / 32;
    float4 ga[4], gb[4];

    // prologue: load stage 0 into registers
    #pragma unroll
    for (int i = 0; i < 4; i++) {
        int f = tid + i * 256, r = f >> 3, c4 = f & 7;
        ga[i] = *(const float4*)&A [(size_t)(row0 + r) * K + c4 * 4];
        gb[i] = *(const float4*)&Bm[(size_t)(col0 + r) * K + c4 * 4];
    }

    for (int ch = 0; ch < nCh; ch++) {
        // ---- convert + store current stage to smem ----
        #pragma unroll
        for (int i = 0; i < 4; i++) {
            int f = tid + i * 256, r = f >> 3, c4 = f & 7;
            int o = r * KSTR + c4 * 2;   // b32 index
            __nv_bfloat16 hx, lx, hy, ly, hz, lz, hw, lw;
            split_bf16(ga[i].x, hx, lx); split_bf16(ga[i].y, hy, ly);
            split_bf16(ga[i].z, hz, lz); split_bf16(ga[i].w, hw, lw);
            ah32[o]     = pack2(hx, hy); ah32[o + 1] = pack2(hz, hw);
            al32[o]     = pack2(lx, ly); al32[o + 1] = pack2(lz, lw);
            split_bf16(gb[i].x, hx, lx); split_bf16(gb[i].y, hy, ly);
            split_bf16(gb[i].z, hz, lz); split_bf16(gb[i].w, hw, lw);
            bh32[o]     = pack2(hx, hy); bh32[o + 1] = pack2(hz, hw);
            bl32[o]     = pack2(lx, ly); bl32[o + 1] = pack2(lz, lw);
        }
        __syncthreads();

        // ---- prefetch next stage (LDGs overlap the MMA work below) ----
        if (ch + 1 < nCh) {
            const int kb = (ch + 1) * 32;
            #pragma unroll
            for (int i = 0; i < 4; i++) {
                int f = tid + i * 256, r = f >> 3, c4 = f & 7;
                ga[i] = *(const float4*)&A [(size_t)(row0 + r) * K + kb + c4 * 4];
                gb[i] = *(const float4*)&Bm[(size_t)(col0 + r) * K + kb + c4 * 4];
            }
        }

        // ---- compute: 2 k16 steps, 3 passes each ----
        #pragma unroll
        for (int s = 0; s < 2; s++) {
            const int kp = s * 8 + lc;
            uint32_t Afh[4][4], Afl[4][4], Bfh[4][2], Bfl[4][2];
            #pragma unroll
            for (int mt = 0; mt < 4; mt++) {
                int r = wm * 64 + mt * 16 + lr;
                int i0 = r * KSTR + kp, i1 = (r + 8) * KSTR + kp;
                Afh[mt][0] = ah32[i0];     Afh[mt][1] = ah32[i1];
                Afh[mt][2] = ah32[i0 + 4]; Afh[mt][3] = ah32[i1 + 4];
                Afl[mt][0] = al32[i0];     Afl[mt][1] = al32[i1];
                Afl[mt][2] = al32[i0 + 4]; Afl[mt][3] = al32[i1 + 4];
            }
            #pragma unroll
            for (int nt = 0; nt < 4; nt++) {
                int n = wn * 32 + nt * 8 + lr;
                int i0 = n * KSTR + kp;
                Bfh[nt][0] = bh32[i0]; Bfh[nt][1] = bh32[i0 + 4];
                Bfl[nt][0] = bl32[i0]; Bfl[nt][1] = bl32[i0 + 4];
            }
            #pragma unroll
            for (int mt = 0; mt < 4; mt++)
                #pragma unroll
                for (int nt = 0; nt < 4; nt++) {
                    MMA_BF16(acc[mt][nt], Afh[mt], Bfh[nt]);
                    MMA_BF16(acc[mt][nt], Afh[mt], Bfl[nt]);
                    MMA_BF16(acc[mt][nt], Afl[mt], Bfh[nt]);
                }
        }
        __syncthreads();
    }

    // ---- epilogue ----
    #pragma unroll
    for (int mt = 0; mt < 4; mt++) {
        #pragma unroll
        for (int nt = 0; nt < 4; nt++) {
            int r = row0 + wm * 64 + mt * 16 + lr;
            int c = col0 + wn * 32 + nt * 8 + lc * 2;
            float2 o0, o1;
            o0.x = acc[mt][nt][0] * alpha; o0.y = acc[mt][nt][1] * alpha;
            o1.x = acc[mt][nt][2] * alpha; o1.y = acc[mt][nt][3] * alpha;
            if (HAS_BIAS) {
                float2 bv = *(const float2*)&bias[c];
                o0.x += bv.x; o0.y += bv.y;
                o1.x += bv.x; o1.y += bv.y;
            }
            if (HAS_RES) {
                float2 r0 = *(const float2*)&R[(size_t)r * N + c];
                float2 r1 = *(const float2*)&R[(size_t)(r + 8) * N + c];
                o0.x += r0.x; o0.y += r0.y;
                o1.x += r1.x; o1.y += r1.y;
            }
            *(float2*)&C[(size_t)r * N + c]       = o0;
            *(float2*)&C[(size_t)(r + 8) * N + c] = o1;
        }
    }
}

// ---------------------------------------------------------------------------
// Tiled transpose: out[c][r] = in[r][c]; batched over z.
// ---------------------------------------------------------------------------
__global__ void transpose_kernel(const float* __restrict__ in,
                                 float* __restrict__ outp, int rows, int cols)
{
    __shared__ float t[32][33];
    const size_t boff = (size_t)blockIdx.z * rows * cols;
    const float* ib = in + boff;
    float* ob = outp + boff;
    int bx = blockIdx.x * 32, by = blockIdx.y * 32;
    int x = threadIdx.x, y = threadIdx.y;
    #pragma unroll
    for (int i = 0; i < 32; i += 8)
        t[y + i][x] = ib[(size_t)(by + y + i) * cols + bx + x];
    __syncthreads();
    #pragma unroll
    for (int i = 0; i < 32; i += 8)
        ob[(size_t)(bx + y + i) * rows + by + x] = t[x][y + i];
}

// ---------------------------------------------------------------------------
// Row softmax over 2048 columns. One block (256 threads) per row.
// ---------------------------------------------------------------------------
__global__ __launch_bounds__(256)
void softmax_kernel(float* __restrict__ S)
{
    float4* row = (float4*)(S + (size_t)blockIdx.x * SEQ);
    const int tid = threadIdx.x;
    __shared__ float red[256];

    float4 v0 = row[tid];
    float4 v1 = row[tid + 256];

    float m = fmaxf(fmaxf(fmaxf(v0.x, v0.y), fmaxf(v0.z, v0.w)),
                    fmaxf(fmaxf(v1.x, v1.y), fmaxf(v1.z, v1.w)));
    red[tid] = m;
    __syncthreads();
    #pragma unroll
    for (int s = 128; s > 0; s >>= 1) {
        if (tid < s) red[tid] = fmaxf(red[tid], red[tid + s]);
        __syncthreads();
    }
    m = red[0];
    __syncthreads();

    v0.x = __expf(v0.x - m); v0.y = __expf(v0.y - m);
    v0.z = __expf(v0.z - m); v0.w = __expf(v0.w - m);
    v1.x = __expf(v1.x - m); v1.y = __expf(v1.y - m);
    v1.z = __expf(v1.z - m); v1.w = __expf(v1.w - m);

    float sum = (v0.x + v0.y + v0.z + v0.w) + (v1.x + v1.y + v1.z + v1.w);
    red[tid] = sum;
    __syncthreads();
    #pragma unroll
    for (int s = 128; s > 0; s >>= 1) {
        if (tid < s) red[tid] += red[tid + s];
        __syncthreads();
    }
    float inv = 1.0f / red[0];

    v0.x *= inv; v0.y *= inv; v0.z *= inv; v0.w *= inv;
    v1.x *= inv; v1.y *= inv; v1.z *= inv; v1.w *= inv;
    row[tid]       = v0;
    row[tid + 256] = v1;
}

// ---------------------------------------------------------------------------
// Host-side plumbing
// ---------------------------------------------------------------------------
extern "C" void kernel_launch(void* const* d_in, const int* in_sizes, int n_in,
                              void* d_out, int out_size)
{
    const float* x_a   = (const float*)d_in[0];
    const float* x_b   = (const float*)d_in[1];
    const float* sa_wq = (const float*)d_in[2];
    const float* sa_bq = (const float*)d_in[3];
    const float* sa_wk = (const float*)d_in[4];
    const float* sa_bk = (const float*)d_in[5];
    const float* sa_wv = (const float*)d_in[6];
    const float* sa_bv = (const float*)d_in[7];
    const float* sa_wo = (const float*)d_in[8];
    const float* sa_bo = (const float*)d_in[9];
    const float* ca_wq = (const float*)d_in[10];
    const float* ca_bq = (const float*)d_in[11];
    const float* ca_wk = (const float*)d_in[12];
    const float* ca_bk = (const float*)d_in[13];
    const float* ca_wv = (const float*)d_in[14];
    const float* ca_bv = (const float*)d_in[15];
    const float* ca_wo = (const float*)d_in[16];
    const float* ca_bo = (const float*)d_in[17];
    float* out = (float*)d_out;

    float *q, *k, *v, *vt, *s, *xb2, *wt;
    cudaGetSymbolAddress((void**)&q,   g_q);
    cudaGetSymbolAddress((void**)&k,   g_k);
    cudaGetSymbolAddress((void**)&v,   g_v);
    cudaGetSymbolAddress((void**)&vt,  g_vt);
    cudaGetSymbolAddress((void**)&s,   g_s);
    cudaGetSymbolAddress((void**)&xb2, g_xb2);
    cudaGetSymbolAddress((void**)&wt,  g_wt);
    float* attn = q;   // alias: q is dead once scores exist

    const int M = BATCH * SEQ;                  // 16384
    const size_t qkvS = (size_t)SEQ * DB;
    const size_t sS   = (size_t)SEQ * SEQ;

    // ---- transpose all weights to [N,K] row-major -------------------------
    float* w_saq = wt + 0 * DB * DB;
    float* w_sak = wt + 1 * DB * DB;
    float* w_sav = wt + 2 * DB * DB;
    float* w_sao = wt + 3 * DB * DB;
    float* w_caq = wt + 4 * DB * DB;  // [DB][DA]
    float* w_cak = wt + 5 * DB * DB;
    float* w_cav = wt + 6 * DB * DB;
    float* w_cao = wt + 7 * DB * DB;
    {
        dim3 b(32, 8);
        dim3 gq(DB / 32, DB / 32, 1);
        transpose_kernel<<<gq, b>>>(sa_wq, w_saq, DB, DB);
        transpose_kernel<<<gq, b>>>(sa_wk, w_sak, DB, DB);
        transpose_kernel<<<gq, b>>>(sa_wv, w_sav, DB, DB);
        transpose_kernel<<<gq, b>>>(sa_wo, w_sao, DB, DB);
        dim3 gc(DB / 32, DA / 32, 1);
        transpose_kernel<<<gc, b>>>(ca_wq, w_caq, DA, DB);
        transpose_kernel<<<gq, b>>>(ca_wk, w_cak, DB, DB);
        transpose_kernel<<<gq, b>>>(ca_wv, w_cav, DB, DB);
        transpose_kernel<<<gq, b>>>(ca_wo, w_cao, DB, DB);
    }

    // ================= Self-attention on x_b ===============================
    {
        dim3 g(DB / 128, M / 128, 1);
        mma_gemm<true, false><<<g, 256, SMEM_DYN>>>(x_b, w_saq, sa_bq, nullptr, q,
                                                    M, DB, DB, 1.0f, 0, 0, 0);
        mma_gemm<true, false><<<g, 256, SMEM_DYN>>>(x_b, w_sak, sa_bk, nullptr, k,
                                                    M, DB, DB, 1.0f, 0, 0, 0);
        mma_gemm<true, false><<<g, 256, SMEM_DYN>>>(x_b, w_sav, sa_bv, nullptr, v,
                                                    M, DB, DB, 1.0f, 0, 0, 0);
    }
    {   // scores = Q @ K^T / 32
        dim3 g(SEQ / 128, SEQ / 128, BATCH);
        mma_gemm<false, false><<<g, 256, SMEM_DYN>>>(q, k, nullptr, nullptr, s,
                                                     SEQ, SEQ, DB,
                                                     1.0f / 32.0f, qkvS, qkvS, sS);
    }
    softmax_kernel<<<BATCH * SEQ, 256>>>(s);
    {   // V^T per batch
        dim3 b(32, 8), g(DB / 32, SEQ / 32, BATCH);
        transpose_kernel<<<g, b>>>(v, vt, SEQ, DB);
    }
    {   // attn = P @ V  (B operand = V^T [DB][SEQ])
        dim3 g(DB / 128, SEQ / 128, BATCH);
        mma_gemm<false, false><<<g, 256, SMEM_DYN>>>(s, vt, nullptr, nullptr, attn,
                                                     SEQ, DB, SEQ,
                                                     1.0f, sS, qkvS, qkvS);
    }
    {   // xb2 = x_b + attn @ Wo + bo
        dim3 g(DB / 128, M / 128, 1);
        mma_gemm<true, true><<<g, 256, SMEM_DYN>>>(attn, w_sao, sa_bo, x_b, xb2,
                                                   M, DB, DB, 1.0f, 0, 0, 0);
    }

    // ================= Cross-attention =====================================
    {
        dim3 g(DB / 128, M / 128, 1);
        mma_gemm<true, false><<<g, 256, SMEM_DYN>>>(x_a, w_caq, ca_bq, nullptr, q,
                                                    M, DB, DA, 1.0f, 0, 0, 0);
        mma_gemm<true, false><<<g, 256, SMEM_DYN>>>(xb2, w_cak, ca_bk, nullptr, k,
                                                    M, DB, DB, 1.0f, 0, 0, 0);
        mma_gemm<true, false><<<g, 256, SMEM_DYN>>>(xb2, w_cav, ca_bv, nullptr, v,
                                                    M, DB, DB, 1.0f, 0, 0, 0);
    }
    {   // scores = Q @ K^T / sqrt(768)
        dim3 g(SEQ / 128, SEQ / 128, BATCH);
        mma_gemm<false, false><<<g, 256, SMEM_DYN>>>(q, k, nullptr, nullptr, s,
                                                     SEQ, SEQ, DB,
                                                     1.0f / sqrtf((float)DA),
                                                     qkvS, qkvS, sS);
    }
    softmax_kernel<<<BATCH * SEQ, 256>>>(s);
    {
        dim3 b(32, 8), g(DB / 32, SEQ / 32, BATCH);
        transpose_kernel<<<g, b>>>(v, vt, SEQ, DB);
    }
    {
        dim3 g(DB / 128, SEQ / 128, BATCH);
        mma_gemm<false, false><<<g, 256, SMEM_DYN>>>(s, vt, nullptr, nullptr, attn,
                                                     SEQ, DB, SEQ,
                                                     1.0f, sS, qkvS, qkvS);
    }
    {   // out = xb2 + attn @ Wo + bo
        dim3 g(DB / 128, M / 128, 1);
        mma_gemm<true, true><<<g, 256, SMEM_DYN>>>(attn, w_cao, ca_bo, xb2, out,
                                                   M, DB, DB, 1.0f, 0, 0, 0);
    }
}